// round 1
// baseline (speedup 1.0000x reference)
#include <cuda_runtime.h>
#include <cuda_bf16.h>

#define NPTS 80000          // 100*100*8
#define H_DIM 100
#define W_DIM 100
#define D_DIM 8
#define NG 1025             // 1024 gaussians + 1 empty
#define NC 18
#define THREADS 256

// Scratch (no cudaMalloc allowed): per-gaussian packed record + feature rows.
// Record layout (16 floats, 64B):
//  [0]=mu.x [1]=mu.y [2]=mu.z [3]=r.x
//  [4]=r.y  [5]=r.z  [6]=opa  [7]=A00
//  [8]=A01  [9]=A02 [10]=A11 [11]=A12
// [12]=A22 [13..15]=pad
__device__ float g_rec[NG * 16];
__device__ float g_feats[NG * NC];

__global__ void precompute_kernel(const float* __restrict__ means,
                                  const float* __restrict__ opac,
                                  const float* __restrict__ scales,
                                  const float* __restrict__ rots,
                                  const float* __restrict__ feats,
                                  const float* __restrict__ empty_scalar) {
    int i = blockIdx.x * blockDim.x + threadIdx.x;
    if (i >= NG) return;

    float mu0, mu1, mu2, r0, r1, r2, op;
    float A00, A01, A02, A11, A12, A22;

    if (i < NG - 1) {
        // quaternion -> rotation
        float qw = rots[i * 4 + 0], qx = rots[i * 4 + 1];
        float qy = rots[i * 4 + 2], qz = rots[i * 4 + 3];
        float inv = rsqrtf(qw * qw + qx * qx + qy * qy + qz * qz);
        qw *= inv; qx *= inv; qy *= inv; qz *= inv;
        float R00 = 1.f - 2.f * (qy * qy + qz * qz);
        float R01 = 2.f * (qx * qy - qw * qz);
        float R02 = 2.f * (qx * qz + qw * qy);
        float R10 = 2.f * (qx * qy + qw * qz);
        float R11 = 1.f - 2.f * (qx * qx + qz * qz);
        float R12 = 2.f * (qy * qz - qw * qx);
        float R20 = 2.f * (qx * qz - qw * qy);
        float R21 = 2.f * (qy * qz + qw * qx);
        float R22 = 1.f - 2.f * (qx * qx + qy * qy);

        float s0 = scales[i * 3 + 0], s1 = scales[i * 3 + 1], s2 = scales[i * 3 + 2];
        float s0q = s0 * s0, s1q = s1 * s1, s2q = s2 * s2;

        // cov = R diag(s^2) R^T (symmetric)
        float a  = s0q * R00 * R00 + s1q * R01 * R01 + s2q * R02 * R02;
        float b  = s0q * R00 * R10 + s1q * R01 * R11 + s2q * R02 * R12;
        float c  = s0q * R00 * R20 + s1q * R01 * R21 + s2q * R02 * R22;
        float dd = s0q * R10 * R10 + s1q * R11 * R11 + s2q * R12 * R12;
        float e  = s0q * R10 * R20 + s1q * R11 * R21 + s2q * R12 * R22;
        float f  = s0q * R20 * R20 + s1q * R21 * R21 + s2q * R22 * R22;

        float det = a * (dd * f - e * e) - b * (b * f - e * c) + c * (b * e - dd * c);
        float idet = 1.0f / det;
        A00 = (dd * f - e * e) * idet;
        A01 = (c * e - b * f) * idet;
        A02 = (b * e - c * dd) * idet;
        A11 = (a * f - c * c) * idet;
        A12 = (b * c - a * e) * idet;
        A22 = (a * dd - b * b) * idet;

        mu0 = means[i * 3 + 0]; mu1 = means[i * 3 + 1]; mu2 = means[i * 3 + 2];
        op = opac[i];
        r0 = 3.f * s0; r1 = 3.f * s1; r2 = 3.f * s2;

        #pragma unroll
        for (int cix = 0; cix < NC - 1; cix++)
            g_feats[i * NC + cix] = feats[i * (NC - 1) + cix];
        g_feats[i * NC + NC - 1] = 0.f;
    } else {
        // synthetic "empty" gaussian: mu = center, cov = diag(rng^2)
        mu0 = 0.f; mu1 = 0.f; mu2 = 2.2f;
        A00 = 1.f / 6400.f; A11 = 1.f / 6400.f; A22 = 1.f / 40.96f;
        A01 = A02 = A12 = 0.f;
        op = 1.f;
        r0 = 240.f; r1 = 240.f; r2 = 19.2f;  // 3 * (80, 80, 6.4)
        #pragma unroll
        for (int cix = 0; cix < NC - 1; cix++)
            g_feats[i * NC + cix] = 0.f;
        g_feats[i * NC + NC - 1] = empty_scalar[0];
    }

    float* rec = g_rec + i * 16;
    rec[0] = mu0; rec[1] = mu1; rec[2]  = mu2; rec[3]  = r0;
    rec[4] = r1;  rec[5] = r2;  rec[6]  = op;  rec[7]  = A00;
    rec[8] = A01; rec[9] = A02; rec[10] = A11; rec[11] = A12;
    rec[12] = A22; rec[13] = 0.f; rec[14] = 0.f; rec[15] = 0.f;
}

__global__ __launch_bounds__(THREADS) void voxelize_kernel(float* __restrict__ out) {
    const int tid = threadIdx.x;
    const int p = blockIdx.x * THREADS + tid;
    const int pc = (p < NPTS) ? p : (NPTS - 1);

    // p = h*(W*D) + w*D + d
    const int h = pc / (W_DIM * D_DIM);
    const int rem = pc - h * (W_DIM * D_DIM);
    const int w = rem >> 3;
    const int d = rem & 7;
    const float x0 = ((float)h + 0.5f) * 0.8f - 40.f;
    const float x1 = ((float)w + 0.5f) * 0.8f - 40.f;
    const float x2 = ((float)d + 0.5f) * 0.8f - 1.f;

    // ---- block bbox reduction ----
    float mn0 = x0, mn1 = x1, mn2 = x2;
    float mx0 = x0, mx1 = x1, mx2 = x2;
    #pragma unroll
    for (int o = 16; o > 0; o >>= 1) {
        mn0 = fminf(mn0, __shfl_xor_sync(0xFFFFFFFFu, mn0, o));
        mn1 = fminf(mn1, __shfl_xor_sync(0xFFFFFFFFu, mn1, o));
        mn2 = fminf(mn2, __shfl_xor_sync(0xFFFFFFFFu, mn2, o));
        mx0 = fmaxf(mx0, __shfl_xor_sync(0xFFFFFFFFu, mx0, o));
        mx1 = fmaxf(mx1, __shfl_xor_sync(0xFFFFFFFFu, mx1, o));
        mx2 = fmaxf(mx2, __shfl_xor_sync(0xFFFFFFFFu, mx2, o));
    }
    __shared__ float smin[8][3], smax[8][3];
    __shared__ float bcen[3], bhalf[3];
    const int wid = tid >> 5, lane = tid & 31;
    if (lane == 0) {
        smin[wid][0] = mn0; smin[wid][1] = mn1; smin[wid][2] = mn2;
        smax[wid][0] = mx0; smax[wid][1] = mx1; smax[wid][2] = mx2;
    }
    __syncthreads();
    if (tid == 0) {
        #pragma unroll
        for (int k = 0; k < 3; k++) {
            float mn = smin[0][k], mx = smax[0][k];
            #pragma unroll
            for (int ww = 1; ww < 8; ww++) {
                mn = fminf(mn, smin[ww][k]);
                mx = fmaxf(mx, smax[ww][k]);
            }
            bcen[k]  = 0.5f * (mn + mx);
            bhalf[k] = 0.5f * (mx - mn);
        }
    }

    // ---- compaction: gaussians overlapping the block bbox ----
    __shared__ int s_cnt;
    __shared__ unsigned short s_list[NG];
    if (tid == 0) s_cnt = 0;
    __syncthreads();
    const float c0 = bcen[0], c1 = bcen[1], c2 = bcen[2];
    const float h0 = bhalf[0], h1 = bhalf[1], h2 = bhalf[2];
    for (int g = tid; g < NG; g += THREADS) {
        const float4 v0 = __ldg((const float4*)(g_rec + g * 16) + 0); // mu.xyz, r.x
        const float4 v1 = __ldg((const float4*)(g_rec + g * 16) + 1); // r.y, r.z, opa, A00
        bool ov = (fabsf(c0 - v0.x) <= h0 + v0.w) &&
                  (fabsf(c1 - v0.y) <= h1 + v1.x) &&
                  (fabsf(c2 - v0.z) <= h2 + v1.y);
        if (ov) {
            int k = atomicAdd(&s_cnt, 1);
            s_list[k] = (unsigned short)g;
        }
    }
    __syncthreads();
    const int cnt = s_cnt;

    // ---- main accumulation over compacted list ----
    float acc[NC];
    #pragma unroll
    for (int c = 0; c < NC; c++) acc[c] = 0.f;

    for (int j = 0; j < cnt; j++) {
        const int g = s_list[j];
        const float4* R4 = (const float4*)(g_rec + g * 16);
        const float4 v0 = __ldg(R4 + 0);   // mu.xyz, r.x
        const float4 v1 = __ldg(R4 + 1);   // r.y, r.z, opa, A00
        const float dx = x0 - v0.x;
        const float dy = x1 - v0.y;
        const float dz = x2 - v0.z;
        if (fabsf(dx) <= v0.w && fabsf(dy) <= v1.x && fabsf(dz) <= v1.y) {
            const float4 v2 = __ldg(R4 + 2);           // A01, A02, A11, A12
            const float A22 = __ldg(g_rec + g * 16 + 12);
            const float A00 = v1.w;
            float maha = A00 * dx * dx + v2.z * dy * dy + A22 * dz * dz
                       + 2.f * (v2.x * dx * dy + v2.y * dx * dz + v2.w * dy * dz);
            float wgt = v1.z * __expf(-0.5f * maha);
            const float2* f2 = (const float2*)(g_feats + g * NC);
            #pragma unroll
            for (int c = 0; c < NC / 2; c++) {
                float2 fv = __ldg(f2 + c);
                acc[2 * c + 0] += wgt * fv.x;
                acc[2 * c + 1] += wgt * fv.y;
            }
        }
    }

    if (p < NPTS) {
        out[p] = 0.f;  // grid_density
        float* o = out + NPTS + (size_t)p * NC;
        #pragma unroll
        for (int c = 0; c < NC; c++) o[c] = acc[c];
    }
}

extern "C" void kernel_launch(void* const* d_in, const int* in_sizes, int n_in,
                              void* d_out, int out_size) {
    const float* means        = (const float*)d_in[0];
    const float* opacities    = (const float*)d_in[1];
    const float* scales       = (const float*)d_in[2];
    const float* rotations    = (const float*)d_in[3];
    const float* features     = (const float*)d_in[4];
    const float* empty_scalar = (const float*)d_in[5];
    float* out = (float*)d_out;

    precompute_kernel<<<(NG + 127) / 128, 128>>>(means, opacities, scales,
                                                 rotations, features, empty_scalar);
    voxelize_kernel<<<(NPTS + THREADS - 1) / THREADS, THREADS>>>(out);
}

// round 2
// speedup vs baseline: 1.0986x; 1.0986x over previous
#include <cuda_runtime.h>
#include <cuda_bf16.h>

#define NPTS 80000          // 100*100*8
#define NG 1025             // 1024 gaussians + 1 synthetic empty
#define NC 18
#define THREADS 128
#define TILE 64
#define PTS_PER_BLOCK 256   // 128 threads x 2 z-points
#define NBLOCKS ((NPTS + PTS_PER_BLOCK - 1) / PTS_PER_BLOCK)   // 313

__global__ __launch_bounds__(THREADS) void voxelize_fused(
    const float* __restrict__ means,
    const float* __restrict__ opac,
    const float* __restrict__ scales,
    const float* __restrict__ rots,
    const float* __restrict__ feats,
    const float* __restrict__ empty_scalar,
    float* __restrict__ out)
{
    const int tid = threadIdx.x;
    const int pbase = blockIdx.x * PTS_PER_BLOCK;

    // thread handles points p0 (d in 0..3) and p0+4 (d+4)
    const int l0 = ((tid >> 2) << 3) | (tid & 3);
    const int p0 = pbase + l0;
    const bool valid = (p0 < NPTS);
    const int pc = valid ? p0 : (NPTS - 1);

    const int hw = pc >> 3;
    const int h = hw / 100;
    const int w = hw - h * 100;
    const float x0  = ((float)h + 0.5f) * 0.8f - 40.f;
    const float x1  = ((float)w + 0.5f) * 0.8f - 40.f;
    const float x2a = ((float)(pc & 7) + 0.5f) * 0.8f - 1.f;
    const float x2b = x2a + 3.2f;

    // ---- block bbox (covers both z points) ----
    float mn0 = x0, mx0 = x0, mn1 = x1, mx1 = x1, mn2 = x2a, mx2 = x2b;
    #pragma unroll
    for (int o = 16; o > 0; o >>= 1) {
        mn0 = fminf(mn0, __shfl_xor_sync(0xFFFFFFFFu, mn0, o));
        mx0 = fmaxf(mx0, __shfl_xor_sync(0xFFFFFFFFu, mx0, o));
        mn1 = fminf(mn1, __shfl_xor_sync(0xFFFFFFFFu, mn1, o));
        mx1 = fmaxf(mx1, __shfl_xor_sync(0xFFFFFFFFu, mx1, o));
        mn2 = fminf(mn2, __shfl_xor_sync(0xFFFFFFFFu, mn2, o));
        mx2 = fmaxf(mx2, __shfl_xor_sync(0xFFFFFFFFu, mx2, o));
    }
    __shared__ float sred[4][6];
    __shared__ float cen0, cen1, cen2, hlf0, hlf1, hlf2;
    const int wid = tid >> 5, lane = tid & 31;
    if (lane == 0) {
        sred[wid][0] = mn0; sred[wid][1] = mx0;
        sred[wid][2] = mn1; sred[wid][3] = mx1;
        sred[wid][4] = mn2; sred[wid][5] = mx2;
    }
    __shared__ int s_cnt;
    if (tid == 0) s_cnt = 0;
    __syncthreads();
    if (tid == 0) {
        float a0 = sred[0][0], b0 = sred[0][1];
        float a1 = sred[0][2], b1 = sred[0][3];
        float a2 = sred[0][4], b2 = sred[0][5];
        #pragma unroll
        for (int k = 1; k < 4; k++) {
            a0 = fminf(a0, sred[k][0]); b0 = fmaxf(b0, sred[k][1]);
            a1 = fminf(a1, sred[k][2]); b1 = fmaxf(b1, sred[k][3]);
            a2 = fminf(a2, sred[k][4]); b2 = fmaxf(b2, sred[k][5]);
        }
        cen0 = 0.5f * (a0 + b0); hlf0 = 0.5f * (b0 - a0);
        cen1 = 0.5f * (a1 + b1); hlf1 = 0.5f * (b1 - a1);
        cen2 = 0.5f * (a2 + b2); hlf2 = 0.5f * (b2 - a2);
    }
    __syncthreads();

    // ---- compaction against block bbox ----
    __shared__ unsigned short s_list[NG];
    {
        const float c0 = cen0, c1 = cen1, c2 = cen2;
        const float h0 = hlf0, h1 = hlf1, h2 = hlf2;
        for (int g = tid; g < NG; g += THREADS) {
            float mux, muy, muz, rx, ry, rz;
            if (g < NG - 1) {
                mux = means[g * 3 + 0]; muy = means[g * 3 + 1]; muz = means[g * 3 + 2];
                rx = 3.f * scales[g * 3 + 0];
                ry = 3.f * scales[g * 3 + 1];
                rz = 3.f * scales[g * 3 + 2];
            } else {
                mux = 0.f; muy = 0.f; muz = 2.2f;
                rx = 240.f; ry = 240.f; rz = 19.2f;
            }
            if (fabsf(c0 - mux) <= h0 + rx &&
                fabsf(c1 - muy) <= h1 + ry &&
                fabsf(c2 - muz) <= h2 + rz) {
                s_list[atomicAdd(&s_cnt, 1)] = (unsigned short)g;
            }
        }
    }
    __syncthreads();
    const int cnt = s_cnt;

    // ---- tiled main loop (records computed on the fly, staged in smem) ----
    // rec layout (14 floats): 0-2 mu, 3-5 r(=3s), 6 opa,
    //   7..12 = a00,a01,a02,a11,a12,a22 with -0.5 and off-diag 2x folded in:
    //   arg(-0.5*maha) = a00 dx^2 + a11 dy^2 + a22 dz^2 + a01 dxdy + a02 dxdz + a12 dydz
    __shared__ float s_rec[TILE][14];
    __shared__ float s_ft[TILE][NC];

    float acc0[NC], acc1[NC];
    #pragma unroll
    for (int c = 0; c < NC; c++) { acc0[c] = 0.f; acc1[c] = 0.f; }

    for (int t0 = 0; t0 < cnt; t0 += TILE) {
        const int n = min(TILE, cnt - t0);
        if (tid < 2 * n) {
            const int s = tid >> 1;
            const int g = s_list[t0 + s];
            if (tid & 1) {
                // stage feature row
                if (g < NG - 1) {
                    const float* fs = feats + g * (NC - 1);
                    #pragma unroll
                    for (int c = 0; c < NC - 1; c++) s_ft[s][c] = __ldg(fs + c);
                    s_ft[s][NC - 1] = 0.f;
                } else {
                    #pragma unroll
                    for (int c = 0; c < NC - 1; c++) s_ft[s][c] = 0.f;
                    s_ft[s][NC - 1] = __ldg(empty_scalar);
                }
            } else {
                // compute record (quat -> R -> cov -> inverse, scaled)
                if (g < NG - 1) {
                    float qw = __ldg(rots + g * 4 + 0), qx = __ldg(rots + g * 4 + 1);
                    float qy = __ldg(rots + g * 4 + 2), qz = __ldg(rots + g * 4 + 3);
                    float inv = rsqrtf(qw * qw + qx * qx + qy * qy + qz * qz);
                    qw *= inv; qx *= inv; qy *= inv; qz *= inv;
                    float R00 = 1.f - 2.f * (qy * qy + qz * qz);
                    float R01 = 2.f * (qx * qy - qw * qz);
                    float R02 = 2.f * (qx * qz + qw * qy);
                    float R10 = 2.f * (qx * qy + qw * qz);
                    float R11 = 1.f - 2.f * (qx * qx + qz * qz);
                    float R12 = 2.f * (qy * qz - qw * qx);
                    float R20 = 2.f * (qx * qz - qw * qy);
                    float R21 = 2.f * (qy * qz + qw * qx);
                    float R22 = 1.f - 2.f * (qx * qx + qy * qy);

                    float s0 = __ldg(scales + g * 3 + 0);
                    float s1 = __ldg(scales + g * 3 + 1);
                    float s2 = __ldg(scales + g * 3 + 2);
                    float s0q = s0 * s0, s1q = s1 * s1, s2q = s2 * s2;

                    float a  = s0q * R00 * R00 + s1q * R01 * R01 + s2q * R02 * R02;
                    float b  = s0q * R00 * R10 + s1q * R01 * R11 + s2q * R02 * R12;
                    float c  = s0q * R00 * R20 + s1q * R01 * R21 + s2q * R02 * R22;
                    float dd = s0q * R10 * R10 + s1q * R11 * R11 + s2q * R12 * R12;
                    float e  = s0q * R10 * R20 + s1q * R11 * R21 + s2q * R12 * R22;
                    float f  = s0q * R20 * R20 + s1q * R21 * R21 + s2q * R22 * R22;

                    float det = a * (dd * f - e * e) - b * (b * f - e * c) + c * (b * e - dd * c);
                    float idet = 1.0f / det;

                    s_rec[s][0] = __ldg(means + g * 3 + 0);
                    s_rec[s][1] = __ldg(means + g * 3 + 1);
                    s_rec[s][2] = __ldg(means + g * 3 + 2);
                    s_rec[s][3] = 3.f * s0;
                    s_rec[s][4] = 3.f * s1;
                    s_rec[s][5] = 3.f * s2;
                    s_rec[s][6] = __ldg(opac + g);
                    s_rec[s][7]  = -0.5f * (dd * f - e * e) * idet;  // a00
                    s_rec[s][8]  = -(c * e - b * f) * idet;          // a01 (2x folded)
                    s_rec[s][9]  = -(b * e - c * dd) * idet;         // a02
                    s_rec[s][10] = -0.5f * (a * f - c * c) * idet;   // a11
                    s_rec[s][11] = -(b * c - a * e) * idet;          // a12
                    s_rec[s][12] = -0.5f * (a * dd - b * b) * idet;  // a22
                } else {
                    s_rec[s][0] = 0.f; s_rec[s][1] = 0.f; s_rec[s][2] = 2.2f;
                    s_rec[s][3] = 240.f; s_rec[s][4] = 240.f; s_rec[s][5] = 19.2f;
                    s_rec[s][6] = 1.f;
                    s_rec[s][7]  = -0.5f / 6400.f;
                    s_rec[s][8]  = 0.f;
                    s_rec[s][9]  = 0.f;
                    s_rec[s][10] = -0.5f / 6400.f;
                    s_rec[s][11] = 0.f;
                    s_rec[s][12] = -0.5f / 40.96f;
                }
            }
        }
        __syncthreads();

        for (int j = 0; j < n; j++) {
            const float* rc = s_rec[j];
            const float dx  = x0  - rc[0];
            const float dy  = x1  - rc[1];
            const float dz0 = x2a - rc[2];
            const float dz1 = x2b - rc[2];
            const bool mxy = (fabsf(dx) <= rc[3]) && (fabsf(dy) <= rc[4]);
            const bool m0 = mxy && (fabsf(dz0) <= rc[5]);
            const bool m1 = mxy && (fabsf(dz1) <= rc[5]);
            if (m0 | m1) {
                const float a00 = rc[7],  a01 = rc[8],  a02 = rc[9];
                const float a11 = rc[10], a12 = rc[11], a22 = rc[12];
                const float common = fmaf(a00, dx * dx, fmaf(a11, dy * dy, a01 * dx * dy));
                const float lin = fmaf(a02, dx, a12 * dy);
                const float arg0 = fmaf(dz0, fmaf(a22, dz0, lin), common);
                const float arg1 = fmaf(dz1, fmaf(a22, dz1, lin), common);
                const float op = rc[6];
                const float w0 = m0 ? op * __expf(arg0) : 0.f;
                const float w1 = m1 ? op * __expf(arg1) : 0.f;
                const float2* f2 = (const float2*)s_ft[j];
                #pragma unroll
                for (int c2 = 0; c2 < NC / 2; c2++) {
                    const float2 fv = f2[c2];
                    acc0[2 * c2 + 0] = fmaf(w0, fv.x, acc0[2 * c2 + 0]);
                    acc0[2 * c2 + 1] = fmaf(w0, fv.y, acc0[2 * c2 + 1]);
                    acc1[2 * c2 + 0] = fmaf(w1, fv.x, acc1[2 * c2 + 0]);
                    acc1[2 * c2 + 1] = fmaf(w1, fv.y, acc1[2 * c2 + 1]);
                }
            }
        }
        __syncthreads();
    }

    // ---- store (density zeros + feature rows for both z points) ----
    if (valid) {
        const int p1 = p0 + 4;
        out[p0] = 0.f;
        out[p1] = 0.f;
        float2* o0 = (float2*)(out + NPTS + (size_t)p0 * NC);
        float2* o1 = (float2*)(out + NPTS + (size_t)p1 * NC);
        #pragma unroll
        for (int c2 = 0; c2 < NC / 2; c2++) {
            o0[c2] = make_float2(acc0[2 * c2], acc0[2 * c2 + 1]);
            o1[c2] = make_float2(acc1[2 * c2], acc1[2 * c2 + 1]);
        }
    }
}

extern "C" void kernel_launch(void* const* d_in, const int* in_sizes, int n_in,
                              void* d_out, int out_size) {
    const float* means        = (const float*)d_in[0];
    const float* opacities    = (const float*)d_in[1];
    const float* scales       = (const float*)d_in[2];
    const float* rotations    = (const float*)d_in[3];
    const float* features     = (const float*)d_in[4];
    const float* empty_scalar = (const float*)d_in[5];
    float* out = (float*)d_out;

    voxelize_fused<<<NBLOCKS, THREADS>>>(means, opacities, scales, rotations,
                                         features, empty_scalar, out);
}

// round 4
// speedup vs baseline: 1.8294x; 1.6652x over previous
#include <cuda_runtime.h>
#include <cuda_bf16.h>

#define NPTS 80000          // 100*100*8
#define NG 1025             // 1024 gaussians + 1 synthetic "empty"
#define NC 18
#define THREADS 128
#define TILE 64

// Block tile: 4h x 4w x 8d = 128 points, 1 point/thread. Grid 25x25 = 625 blocks.
// Thread map: dd = tid&7, ww = (tid>>3)&3, hh = tid>>5 (== warp id).

__global__ __launch_bounds__(THREADS) void voxelize(
    const float* __restrict__ means,
    const float* __restrict__ opac,
    const float* __restrict__ scales,
    const float* __restrict__ rots,
    const float* __restrict__ feats,
    const float* __restrict__ empty_scalar,
    float* __restrict__ out)
{
    const int tid = threadIdx.x;
    const int bh = blockIdx.x, bw = blockIdx.y;
    const int dd = tid & 7;
    const int ww = (tid >> 3) & 3;
    const int hh = tid >> 5;            // warp id: one h-slab per warp
    const int h = 4 * bh + hh;
    const int w = 4 * bw + ww;
    const int p = h * 800 + w * 8 + dd;

    // match reference rounding: (i+0.5)*0.8 + lo, no fma contraction
    const float px = __fadd_rn(__fmul_rn((float)h + 0.5f, 0.8f), -40.f);
    const float py = __fadd_rn(__fmul_rn((float)w + 0.5f, 0.8f), -40.f);
    const float pz = __fadd_rn(__fmul_rn((float)dd + 0.5f, 0.8f), -1.f);

    // analytic block bbox (conservative, eps-padded)
    const float EPS = 1e-3f;
    const float bcx = (4.f * (float)bh + 2.f) * 0.8f - 40.f;   // half 1.2
    const float bcy = (4.f * (float)bw + 2.f) * 0.8f - 40.f;   // half 1.2
    const float BH  = 1.2f + EPS;
    const float BHZ = 2.8f + EPS;                               // z center 2.2

    __shared__ unsigned short s_list[NG];
    __shared__ int s_cnt;
    if (tid == 0) s_cnt = 0;
    __syncthreads();

    // ---- block-level compaction against analytic bbox ----
    for (int g = tid; g < NG; g += THREADS) {
        float mux, muy, muz, rx, ry, rz;
        if (g < NG - 1) {
            mux = __ldg(means + 3 * g);
            muy = __ldg(means + 3 * g + 1);
            muz = __ldg(means + 3 * g + 2);
            rx = 3.f * __ldg(scales + 3 * g);
            ry = 3.f * __ldg(scales + 3 * g + 1);
            rz = 3.f * __ldg(scales + 3 * g + 2);
        } else {
            mux = 0.f; muy = 0.f; muz = 2.2f;
            rx = 240.f; ry = 240.f; rz = 19.2f;
        }
        if (fabsf(bcx - mux) <= BH + rx &&
            fabsf(bcy - muy) <= BH + ry &&
            fabsf(2.2f - muz) <= BHZ + rz) {
            s_list[atomicAdd(&s_cnt, 1)] = (unsigned short)g;
        }
    }
    __syncthreads();
    const int cnt = s_cnt;

    // rec layout (16 floats/row, float4-aligned):
    //  [0..2]=mu  [3]=rx  [4]=ry  [5]=rz  [6]=lopa  [7]=pad
    //  [8]=a00 [9]=a01 [10]=a02 [11]=a11  [12]=a12 [13]=a22  (pads 14,15)
    //  a_ij carry -0.5 and the off-diagonal 2x folded in:
    //  arg = lopa + a00 dx^2 + a11 dy^2 + a22 dz^2 + a01 dxdy + a02 dxdz + a12 dydz
    __shared__ __align__(16) float s_rec[TILE][16];
    __shared__ __align__(16) float s_ft[TILE][20];   // row = 80B, multiple of 16

    float acc[NC];
    #pragma unroll
    for (int c = 0; c < NC; c++) acc[c] = 0.f;

    for (int t0 = 0; t0 < cnt; t0 += TILE) {
        const int n = min(TILE, cnt - t0);

        // ---- staging: tid<n -> record; 64<=tid<64+n -> features ----
        if (tid < n) {
            const int g = s_list[t0 + tid];
            float* rc = s_rec[tid];
            if (g < NG - 1) {
                float qw = __ldg(rots + g * 4 + 0), qx = __ldg(rots + g * 4 + 1);
                float qy = __ldg(rots + g * 4 + 2), qz = __ldg(rots + g * 4 + 3);
                float inv = rsqrtf(qw * qw + qx * qx + qy * qy + qz * qz);
                qw *= inv; qx *= inv; qy *= inv; qz *= inv;
                float R00 = 1.f - 2.f * (qy * qy + qz * qz);
                float R01 = 2.f * (qx * qy - qw * qz);
                float R02 = 2.f * (qx * qz + qw * qy);
                float R10 = 2.f * (qx * qy + qw * qz);
                float R11 = 1.f - 2.f * (qx * qx + qz * qz);
                float R12 = 2.f * (qy * qz - qw * qx);
                float R20 = 2.f * (qx * qz - qw * qy);
                float R21 = 2.f * (qy * qz + qw * qx);
                float R22 = 1.f - 2.f * (qx * qx + qy * qy);

                float s0 = __ldg(scales + g * 3 + 0);
                float s1 = __ldg(scales + g * 3 + 1);
                float s2 = __ldg(scales + g * 3 + 2);
                float s0q = s0 * s0, s1q = s1 * s1, s2q = s2 * s2;

                float a  = s0q * R00 * R00 + s1q * R01 * R01 + s2q * R02 * R02;
                float b  = s0q * R00 * R10 + s1q * R01 * R11 + s2q * R02 * R12;
                float c  = s0q * R00 * R20 + s1q * R01 * R21 + s2q * R02 * R22;
                float dd_ = s0q * R10 * R10 + s1q * R11 * R11 + s2q * R12 * R12;
                float e  = s0q * R10 * R20 + s1q * R11 * R21 + s2q * R12 * R22;
                float f  = s0q * R20 * R20 + s1q * R21 * R21 + s2q * R22 * R22;

                float det = a * (dd_ * f - e * e) - b * (b * f - e * c) + c * (b * e - dd_ * c);
                float idet = 1.0f / det;

                rc[0] = __ldg(means + g * 3 + 0);
                rc[1] = __ldg(means + g * 3 + 1);
                rc[2] = __ldg(means + g * 3 + 2);
                rc[3] = 3.f * s0;
                rc[4] = 3.f * s1;
                rc[5] = 3.f * s2;
                rc[6] = __logf(__ldg(opac + g));
                rc[7] = 0.f;
                rc[8]  = -0.5f * (dd_ * f - e * e) * idet;   // a00
                rc[9]  = -(c * e - b * f) * idet;            // a01 (2x folded)
                rc[10] = -(b * e - c * dd_) * idet;          // a02
                rc[11] = -0.5f * (a * f - c * c) * idet;     // a11
                rc[12] = -(b * c - a * e) * idet;            // a12
                rc[13] = -0.5f * (a * dd_ - b * b) * idet;   // a22
            } else {
                rc[0] = 0.f; rc[1] = 0.f; rc[2] = 2.2f;
                rc[3] = 240.f; rc[4] = 240.f; rc[5] = 19.2f;
                rc[6] = 0.f;  rc[7] = 0.f;
                rc[8]  = -0.5f / 6400.f;
                rc[9]  = 0.f;
                rc[10] = 0.f;
                rc[11] = -0.5f / 6400.f;
                rc[12] = 0.f;
                rc[13] = -0.5f / 40.96f;
            }
        } else if (tid >= 64 && tid < 64 + n) {
            const int s = tid - 64;
            const int g = s_list[t0 + s];
            float* ft = s_ft[s];
            if (g < NG - 1) {
                const float* fs = feats + (size_t)g * (NC - 1);
                #pragma unroll
                for (int c = 0; c < NC - 1; c++) ft[c] = __ldg(fs + c);
                ft[NC - 1] = 0.f;
            } else {
                #pragma unroll
                for (int c = 0; c < NC - 1; c++) ft[c] = 0.f;
                ft[NC - 1] = __ldg(empty_scalar);
            }
        }
        __syncthreads();

        // ---- warp-level sub-cull (ballot) + evaluation ----
        for (int base = 0; base < n; base += 32) {
            const int s = base + (tid & 31);
            bool ok = false;
            if (s < n) {
                const float4 v0 = *(const float4*)&s_rec[s][0];   // mu, rx
                const float4 v1 = *(const float4*)&s_rec[s][4];   // ry, rz, lopa
                ok = (fabsf(px   - v0.x) <= v0.w + EPS) &&        // warp x half = 0
                     (fabsf(bcy  - v0.y) <= BH   + v1.x) &&
                     (fabsf(2.2f - v0.z) <= BHZ  + v1.y);
            }
            unsigned mbits = __ballot_sync(0xFFFFFFFFu, ok);
            while (mbits) {
                const int j = base + (__ffs(mbits) - 1);
                mbits &= mbits - 1;
                const float4 v0 = *(const float4*)&s_rec[j][0];
                const float4 v1 = *(const float4*)&s_rec[j][4];
                const float dx = px - v0.x;
                const float dy = py - v0.y;
                const float dz = pz - v0.z;
                if (fabsf(dx) <= v0.w && fabsf(dy) <= v1.x && fabsf(dz) <= v1.y) {
                    const float4 v2 = *(const float4*)&s_rec[j][8];   // a00,a01,a02,a11
                    const float2 v3 = *(const float2*)&s_rec[j][12];  // a12,a22
                    float t1 = fmaf(v2.y, dy, v2.x * dx);
                    t1 = fmaf(v2.z, dz, t1);
                    const float t2 = fmaf(v3.x, dz, v2.w * dy);
                    float arg = fmaf(v3.y * dz, dz, v1.z);
                    arg = fmaf(dy, t2, arg);
                    arg = fmaf(dx, t1, arg);
                    const float wgt = __expf(arg);
                    #pragma unroll
                    for (int q = 0; q < 4; q++) {
                        const float4 fv = *(const float4*)&s_ft[j][4 * q];
                        acc[4 * q + 0] = fmaf(wgt, fv.x, acc[4 * q + 0]);
                        acc[4 * q + 1] = fmaf(wgt, fv.y, acc[4 * q + 1]);
                        acc[4 * q + 2] = fmaf(wgt, fv.z, acc[4 * q + 2]);
                        acc[4 * q + 3] = fmaf(wgt, fv.w, acc[4 * q + 3]);
                    }
                    const float2 fv2 = *(const float2*)&s_ft[j][16];
                    acc[16] = fmaf(wgt, fv2.x, acc[16]);
                    acc[17] = fmaf(wgt, fv2.y, acc[17]);
                }
            }
        }
        __syncthreads();
    }

    // ---- stores: density zero + 18 feature channels ----
    out[p] = 0.f;
    float2* o = (float2*)(out + NPTS + (size_t)p * NC);
    #pragma unroll
    for (int c2 = 0; c2 < NC / 2; c2++)
        o[c2] = make_float2(acc[2 * c2], acc[2 * c2 + 1]);
}

extern "C" void kernel_launch(void* const* d_in, const int* in_sizes, int n_in,
                              void* d_out, int out_size) {
    const float* means        = (const float*)d_in[0];
    const float* opacities    = (const float*)d_in[1];
    const float* scales       = (const float*)d_in[2];
    const float* rotations    = (const float*)d_in[3];
    const float* features     = (const float*)d_in[4];
    const float* empty_scalar = (const float*)d_in[5];
    float* out = (float*)d_out;

    dim3 grid(25, 25);
    voxelize<<<grid, THREADS>>>(means, opacities, scales, rotations,
                                features, empty_scalar, out);
}

// round 5
// speedup vs baseline: 2.0760x; 1.1348x over previous
#include <cuda_runtime.h>
#include <cuda_bf16.h>

#define NPTS 80000          // 100*100*8
#define NG 1025             // 1024 gaussians + 1 synthetic "empty"
#define NC 18
#define THREADS 256
#define TILE 64

// Block tile: 4h x 4w x 8d = 128 points. 2 threads per point (gaussian-split).
// pt = tid & 127: dd = pt&7, ww = (pt>>3)&3, hh = pt>>5. half = tid>>7.
// Warps 0-3 (half 0) and 4-7 (half 1) cover the same 128 points.

__global__ __launch_bounds__(THREADS) void voxelize(
    const float* __restrict__ means,
    const float* __restrict__ opac,
    const float* __restrict__ scales,
    const float* __restrict__ rots,
    const float* __restrict__ feats,
    const float* __restrict__ empty_scalar,
    float* __restrict__ out)
{
    const int tid = threadIdx.x;
    const int lane = tid & 31;
    const int pt = tid & 127;
    const int half = tid >> 7;
    const int bh = blockIdx.x, bw = blockIdx.y;
    const int dd = pt & 7;
    const int ww = (pt >> 3) & 3;
    const int hh = pt >> 5;             // h-slab: warp-uniform
    const int h = 4 * bh + hh;
    const int w = 4 * bw + ww;
    const int p = h * 800 + w * 8 + dd;

    // match reference rounding: (i+0.5)*0.8 + lo, no fma contraction
    const float px = __fadd_rn(__fmul_rn((float)h + 0.5f, 0.8f), -40.f);
    const float py = __fadd_rn(__fmul_rn((float)w + 0.5f, 0.8f), -40.f);
    const float pz = __fadd_rn(__fmul_rn((float)dd + 0.5f, 0.8f), -1.f);

    // analytic block bbox (conservative, eps-padded); z center 2.2, half 2.8
    const float EPS = 1e-3f;
    const float bcx = (4.f * (float)bh + 2.f) * 0.8f - 40.f;   // half 1.2
    const float bcy = (4.f * (float)bw + 2.f) * 0.8f - 40.f;   // half 1.2
    const float BH  = 1.2f + EPS;
    const float BHZ = 2.8f + EPS;

    __shared__ unsigned short s_list[NG];
    __shared__ int s_cnt;
    if (tid == 0) s_cnt = 0;
    __syncthreads();

    // ---- block-level compaction (4 unrolled iters, 24 LDGs in flight) ----
    {
        float mx[4], my[4], mz[4], sx[4], sy[4], sz[4];
        #pragma unroll
        for (int it = 0; it < 4; it++) {
            const int g = tid + it * 256;          // < 1024 always
            mx[it] = __ldg(means + 3 * g);
            my[it] = __ldg(means + 3 * g + 1);
            mz[it] = __ldg(means + 3 * g + 2);
            sx[it] = __ldg(scales + 3 * g);
            sy[it] = __ldg(scales + 3 * g + 1);
            sz[it] = __ldg(scales + 3 * g + 2);
        }
        #pragma unroll
        for (int it = 0; it < 4; it++) {
            const int g = tid + it * 256;
            if (fabsf(bcx - mx[it]) <= BH + 3.f * sx[it] &&
                fabsf(bcy - my[it]) <= BH + 3.f * sy[it] &&
                fabsf(2.2f - mz[it]) <= BHZ + 3.f * sz[it]) {
                s_list[atomicAdd(&s_cnt, 1)] = (unsigned short)g;
            }
        }
        if (tid == 0)   // synthetic gaussian covers the whole volume: always in
            s_list[atomicAdd(&s_cnt, 1)] = (unsigned short)(NG - 1);
    }
    __syncthreads();
    const int cnt = s_cnt;

    // rec layout (16 floats/row): [0..2]=mu [3]=rx [4]=ry [5]=rz [6]=lopa [7]=pad
    //   [8]=a00 [9]=a01 [10]=a02 [11]=a11 [12]=a12 [13]=a22  (-0.5 & off-diag 2x folded)
    //   arg = lopa + a00 dx^2 + a11 dy^2 + a22 dz^2 + a01 dxdy + a02 dxdz + a12 dydz
    // s_pool aliases: [0, TILE*16) = s_rec; [TILE*16, TILE*36) = s_ft rows of 20.
    // After the tile loop the whole pool (TILE*36 = 2304 = 128*18) becomes the
    // cross-half reduction buffer.
    __shared__ __align__(16) float s_pool[TILE * 36];
    float* const s_rec = s_pool;                 // [TILE][16]
    float* const s_ft  = s_pool + TILE * 16;     // [TILE][20]

    float acc[NC];
    #pragma unroll
    for (int c = 0; c < NC; c++) acc[c] = 0.f;

    for (int t0 = 0; t0 < cnt; t0 += TILE) {
        const int n = min(TILE, cnt - t0);

        // ---- staging: tid<n -> record (warps 0-2); 128<=tid<128+n -> feats ----
        if (tid < n) {
            const int g = s_list[t0 + tid];
            float* rc = s_rec + tid * 16;
            if (g < NG - 1) {
                float qw = __ldg(rots + g * 4 + 0), qx = __ldg(rots + g * 4 + 1);
                float qy = __ldg(rots + g * 4 + 2), qz = __ldg(rots + g * 4 + 3);
                float inv = rsqrtf(qw * qw + qx * qx + qy * qy + qz * qz);
                qw *= inv; qx *= inv; qy *= inv; qz *= inv;
                float R00 = 1.f - 2.f * (qy * qy + qz * qz);
                float R01 = 2.f * (qx * qy - qw * qz);
                float R02 = 2.f * (qx * qz + qw * qy);
                float R10 = 2.f * (qx * qy + qw * qz);
                float R11 = 1.f - 2.f * (qx * qx + qz * qz);
                float R12 = 2.f * (qy * qz - qw * qx);
                float R20 = 2.f * (qx * qz - qw * qy);
                float R21 = 2.f * (qy * qz + qw * qx);
                float R22 = 1.f - 2.f * (qx * qx + qy * qy);

                float s0 = __ldg(scales + g * 3 + 0);
                float s1 = __ldg(scales + g * 3 + 1);
                float s2 = __ldg(scales + g * 3 + 2);
                float s0q = s0 * s0, s1q = s1 * s1, s2q = s2 * s2;

                float a  = s0q * R00 * R00 + s1q * R01 * R01 + s2q * R02 * R02;
                float b  = s0q * R00 * R10 + s1q * R01 * R11 + s2q * R02 * R12;
                float c  = s0q * R00 * R20 + s1q * R01 * R21 + s2q * R02 * R22;
                float dd_ = s0q * R10 * R10 + s1q * R11 * R11 + s2q * R12 * R12;
                float e  = s0q * R10 * R20 + s1q * R11 * R21 + s2q * R12 * R22;
                float f  = s0q * R20 * R20 + s1q * R21 * R21 + s2q * R22 * R22;

                float det = a * (dd_ * f - e * e) - b * (b * f - e * c) + c * (b * e - dd_ * c);
                float idet = 1.0f / det;

                rc[0] = __ldg(means + g * 3 + 0);
                rc[1] = __ldg(means + g * 3 + 1);
                rc[2] = __ldg(means + g * 3 + 2);
                rc[3] = 3.f * s0;
                rc[4] = 3.f * s1;
                rc[5] = 3.f * s2;
                rc[6] = __logf(__ldg(opac + g));
                rc[7] = 0.f;
                rc[8]  = -0.5f * (dd_ * f - e * e) * idet;   // a00
                rc[9]  = -(c * e - b * f) * idet;            // a01 (2x folded)
                rc[10] = -(b * e - c * dd_) * idet;          // a02
                rc[11] = -0.5f * (a * f - c * c) * idet;     // a11
                rc[12] = -(b * c - a * e) * idet;            // a12
                rc[13] = -0.5f * (a * dd_ - b * b) * idet;   // a22
            } else {
                rc[0] = 0.f; rc[1] = 0.f; rc[2] = 2.2f;
                rc[3] = 240.f; rc[4] = 240.f; rc[5] = 19.2f;
                rc[6] = 0.f;  rc[7] = 0.f;
                rc[8]  = -0.5f / 6400.f;
                rc[9]  = 0.f;
                rc[10] = 0.f;
                rc[11] = -0.5f / 6400.f;
                rc[12] = 0.f;
                rc[13] = -0.5f / 40.96f;
            }
        } else if (tid >= 128 && tid < 128 + n) {
            const int s = tid - 128;
            const int g = s_list[t0 + s];
            float* ft = s_ft + s * 20;
            if (g < NG - 1) {
                const float* fs = feats + (size_t)g * (NC - 1);
                #pragma unroll
                for (int c = 0; c < NC - 1; c++) ft[c] = __ldg(fs + c);
                ft[NC - 1] = 0.f;
            } else {
                #pragma unroll
                for (int c = 0; c < NC - 1; c++) ft[c] = 0.f;
                ft[NC - 1] = __ldg(empty_scalar);
            }
        }
        __syncthreads();

        // ---- warp-level sub-cull + eval over this half's sub-range ----
        const int nh = n >> 1;
        const int lo = half ? nh : 0;
        const int hi = half ? n : nh;
        for (int base = lo; base < hi; base += 32) {
            const int s = base + lane;
            bool ok = false;
            if (s < hi) {
                const float4 v0 = *(const float4*)(s_rec + s * 16);      // mu, rx
                const float4 v1 = *(const float4*)(s_rec + s * 16 + 4);  // ry, rz, lopa
                ok = (fabsf(px   - v0.x) <= v0.w + EPS) &&               // warp x half = 0
                     (fabsf(bcy  - v0.y) <= BH   + v1.x) &&
                     (fabsf(2.2f - v0.z) <= BHZ  + v1.y);
            }
            unsigned mbits = __ballot_sync(0xFFFFFFFFu, ok);
            while (mbits) {
                const int j = base + (__ffs(mbits) - 1);
                mbits &= mbits - 1;
                const float4 v0 = *(const float4*)(s_rec + j * 16);
                const float4 v1 = *(const float4*)(s_rec + j * 16 + 4);
                const float dx = px - v0.x;
                const float dy = py - v0.y;
                const float dz = pz - v0.z;
                if (fabsf(dx) <= v0.w && fabsf(dy) <= v1.x && fabsf(dz) <= v1.y) {
                    const float4 v2 = *(const float4*)(s_rec + j * 16 + 8);   // a00,a01,a02,a11
                    const float2 v3 = *(const float2*)(s_rec + j * 16 + 12);  // a12,a22
                    float t1 = fmaf(v2.y, dy, v2.x * dx);
                    t1 = fmaf(v2.z, dz, t1);
                    const float t2 = fmaf(v3.x, dz, v2.w * dy);
                    float arg = fmaf(v3.y * dz, dz, v1.z);
                    arg = fmaf(dy, t2, arg);
                    arg = fmaf(dx, t1, arg);
                    const float wgt = __expf(arg);
                    const float* ft = s_ft + j * 20;
                    #pragma unroll
                    for (int q = 0; q < 4; q++) {
                        const float4 fv = *(const float4*)(ft + 4 * q);
                        acc[4 * q + 0] = fmaf(wgt, fv.x, acc[4 * q + 0]);
                        acc[4 * q + 1] = fmaf(wgt, fv.y, acc[4 * q + 1]);
                        acc[4 * q + 2] = fmaf(wgt, fv.z, acc[4 * q + 2]);
                        acc[4 * q + 3] = fmaf(wgt, fv.w, acc[4 * q + 3]);
                    }
                    const float2 fv2 = *(const float2*)(ft + 16);
                    acc[16] = fmaf(wgt, fv2.x, acc[16]);
                    acc[17] = fmaf(wgt, fv2.y, acc[17]);
                }
            }
        }
        __syncthreads();
    }

    // ---- cross-half reduction through the (now dead) staging pool ----
    if (half == 1) {
        float* r = s_pool + pt * NC;
        #pragma unroll
        for (int c = 0; c < NC; c++) r[c] = acc[c];
    }
    __syncthreads();
    if (half == 0) {
        const float* r = s_pool + pt * NC;
        out[p] = 0.f;   // grid_density
        float2* o = (float2*)(out + NPTS + (size_t)p * NC);
        #pragma unroll
        for (int c2 = 0; c2 < NC / 2; c2++)
            o[c2] = make_float2(acc[2 * c2] + r[2 * c2],
                                acc[2 * c2 + 1] + r[2 * c2 + 1]);
    }
}

extern "C" void kernel_launch(void* const* d_in, const int* in_sizes, int n_in,
                              void* d_out, int out_size) {
    const float* means        = (const float*)d_in[0];
    const float* opacities    = (const float*)d_in[1];
    const float* scales       = (const float*)d_in[2];
    const float* rotations    = (const float*)d_in[3];
    const float* features     = (const float*)d_in[4];
    const float* empty_scalar = (const float*)d_in[5];
    float* out = (float*)d_out;

    dim3 grid(25, 25);
    voxelize<<<grid, THREADS>>>(means, opacities, scales, rotations,
                                features, empty_scalar, out);
}